// round 1
// baseline (speedup 1.0000x reference)
#include <cuda_runtime.h>
#include <cuda_fp16.h>

#define N_TOK 16384
#define C_DIM 896
#define RH_DIM 448
#define E_NUM 3
#define H_DIM 3136
#define ROUTER_TAU 2e-3f

#define BM 128
#define BN 128
#define BK 32

// ---------------- scratch (__device__ globals; no allocation allowed) ----------------
__device__ __align__(256) __half g_x16[N_TOK * C_DIM];
__device__ __align__(256) __half g_xperm[N_TOK * C_DIM];
__device__ __align__(256) __half g_w1[C_DIM * RH_DIM];
__device__ __align__(256) __half g_win[E_NUM * C_DIM * H_DIM];
__device__ __align__(256) __half g_wout[E_NUM * H_DIM * C_DIM];
__device__ __align__(256) __half g_hid[N_TOK * RH_DIM];
__device__ __align__(256) __half g_h[(size_t)N_TOK * H_DIM];
__device__ int g_expert[N_TOK];
__device__ int g_tok_of_rank[N_TOK];
__device__ int g_flaglist[N_TOK];
__device__ int g_cnt[E_NUM];
__device__ int g_pos[E_NUM];
__device__ int g_off[E_NUM + 1];
__device__ int g_nflag;

__device__ __forceinline__ unsigned smem_u32(const void* p) {
    return (unsigned)__cvta_generic_to_shared(p);
}

// ---------------- init ----------------
__global__ void k_init() {
    if (threadIdx.x < E_NUM) { g_cnt[threadIdx.x] = 0; g_pos[threadIdx.x] = 0; }
    if (threadIdx.x == 0) g_nflag = 0;
}

// ---------------- fp32 -> fp16 casts ----------------
// WHICH: 0=x->g_x16, 1=rw1->g_w1, 2=ew_in->g_win, 3=ew_out->g_wout
template <int WHICH>
__global__ void k_cast(const float4* __restrict__ src, int n4) {
    __half2* dst = (WHICH == 0) ? (__half2*)g_x16
                 : (WHICH == 1) ? (__half2*)g_w1
                 : (WHICH == 2) ? (__half2*)g_win
                                : (__half2*)g_wout;
    int i = blockIdx.x * blockDim.x + threadIdx.x;
    if (i < n4) {
        float4 v = src[i];
        dst[2 * i + 0] = __floats2half2_rn(v.x, v.y);
        dst[2 * i + 1] = __floats2half2_rn(v.z, v.w);
    }
}

// ---------------- generic fp16 GEMM: C = act(A @ B + bias) ----------------
// EPI 0: router  A=g_x16   [16384,C], B=g_w1   [C,RH],  relu -> g_hid (fp16)
// EPI 1: expert1 A=g_xperm (grouped), B=g_win[e][C,H],  relu -> g_h   (fp16)
// EPI 2: expert2 A=g_h     (grouped), B=g_wout[e][H,C], +bias+residual -> out fp32 (scatter)
template <int EPI>
__global__ void __launch_bounds__(256) k_gemm(
    const float* __restrict__ bias0, int M0, int N, int K,
    const float* __restrict__ xres, float* __restrict__ outp)
{
    int e = (EPI == 0) ? 0 : blockIdx.z;
    int m_off = 0, M = M0;
    if (EPI != 0) { m_off = g_off[e]; M = g_off[e + 1] - m_off; }
    int m0 = blockIdx.x * BM;
    if (m0 >= M) return;
    int n0 = blockIdx.y * BN;

    const __half* Abase = (EPI == 0) ? g_x16 : (EPI == 1) ? g_xperm : g_h;
    const __half* Bbase = (EPI == 0) ? g_w1 : (EPI == 1) ? g_win : g_wout;
    __half* out16 = (EPI == 0) ? g_hid : g_h;

    const __half* A = Abase + (size_t)m_off * K;
    const __half* B = Bbase + (size_t)e * K * N;
    const float* bias = bias0 + (size_t)e * N;

    __shared__ __half sA[2][BM][BK + 8];
    __shared__ __half sB[2][BK][BN + 8];

    int tid = threadIdx.x, lane = tid & 31, warp = tid >> 5;
    int wm = warp & 3, wn = warp >> 2;  // 4 M-warps x 2 N-warps; warp tile 32x64

    float acc[2][8][4];
#pragma unroll
    for (int i = 0; i < 2; i++)
#pragma unroll
        for (int j = 0; j < 8; j++)
#pragma unroll
            for (int k = 0; k < 4; k++) acc[i][j][k] = 0.f;

    int KT = K / BK;

    auto load_stage = [&](int kt, int buf) {
        int k0 = kt * BK;
#pragma unroll
        for (int i = 0; i < 2; i++) {
            int q = tid + i * 256;
            int row = q >> 2, kc = (q & 3) * 8;
            int gm = m0 + row;
            const __half* src = A + (size_t)(gm < M ? gm : (M - 1)) * K + k0 + kc;
            unsigned dst = smem_u32(&sA[buf][row][kc]);
            int sz = (gm < M) ? 16 : 0;
            asm volatile("cp.async.cg.shared.global [%0],[%1],16,%2;\n" ::"r"(dst), "l"(src), "r"(sz));
        }
#pragma unroll
        for (int i = 0; i < 2; i++) {
            int q = tid + i * 256;
            int kr = q >> 4, nc = (q & 15) * 8;
            int gn = n0 + nc;
            const __half* src = B + (size_t)(k0 + kr) * N + (gn < N ? gn : (N - 8));
            unsigned dst = smem_u32(&sB[buf][kr][nc]);
            int sz = (gn < N) ? 16 : 0;
            asm volatile("cp.async.cg.shared.global [%0],[%1],16,%2;\n" ::"r"(dst), "l"(src), "r"(sz));
        }
        asm volatile("cp.async.commit_group;\n");
    };

    auto compute_stage = [&](int buf) {
#pragma unroll
        for (int ks = 0; ks < 2; ks++) {
            unsigned a[2][4], b[4][4];
            int lrow = lane & 15, lcol = (lane >> 4) * 8;
#pragma unroll
            for (int mi = 0; mi < 2; mi++) {
                unsigned addr = smem_u32(&sA[buf][wm * 32 + mi * 16 + lrow][ks * 16 + lcol]);
                asm volatile("ldmatrix.sync.aligned.m8n8.x4.shared.b16 {%0,%1,%2,%3},[%4];\n"
                             : "=r"(a[mi][0]), "=r"(a[mi][1]), "=r"(a[mi][2]), "=r"(a[mi][3])
                             : "r"(addr));
            }
#pragma unroll
            for (int nq = 0; nq < 4; nq++) {
                unsigned addr = smem_u32(&sB[buf][ks * 16 + lrow][wn * 64 + nq * 16 + lcol]);
                asm volatile("ldmatrix.sync.aligned.m8n8.x4.trans.shared.b16 {%0,%1,%2,%3},[%4];\n"
                             : "=r"(b[nq][0]), "=r"(b[nq][1]), "=r"(b[nq][2]), "=r"(b[nq][3])
                             : "r"(addr));
            }
#pragma unroll
            for (int mi = 0; mi < 2; mi++)
#pragma unroll
                for (int ni = 0; ni < 8; ni++) {
                    unsigned b0 = b[ni >> 1][(ni & 1) * 2], b1 = b[ni >> 1][(ni & 1) * 2 + 1];
                    asm volatile(
                        "mma.sync.aligned.m16n8k16.row.col.f32.f16.f16.f32 "
                        "{%0,%1,%2,%3},{%4,%5,%6,%7},{%8,%9},{%0,%1,%2,%3};\n"
                        : "+f"(acc[mi][ni][0]), "+f"(acc[mi][ni][1]),
                          "+f"(acc[mi][ni][2]), "+f"(acc[mi][ni][3])
                        : "r"(a[mi][0]), "r"(a[mi][1]), "r"(a[mi][2]), "r"(a[mi][3]),
                          "r"(b0), "r"(b1));
                }
        }
    };

    load_stage(0, 0);
    int buf = 0;
    for (int kt = 0; kt < KT; kt++) {
        if (kt + 1 < KT) {
            load_stage(kt + 1, buf ^ 1);
            asm volatile("cp.async.wait_group 1;\n");
        } else {
            asm volatile("cp.async.wait_group 0;\n");
        }
        __syncthreads();
        compute_stage(buf);
        buf ^= 1;
        __syncthreads();
    }

    // epilogue
#pragma unroll
    for (int mi = 0; mi < 2; mi++)
#pragma unroll
        for (int ni = 0; ni < 8; ni++) {
            int r0 = wm * 32 + mi * 16 + (lane >> 2);
            int c = n0 + wn * 64 + ni * 8 + (lane & 3) * 2;
            if (c >= N) continue;
#pragma unroll
            for (int rr = 0; rr < 2; rr++) {
                int m = m0 + r0 + rr * 8;
                if (m >= M) continue;
                float v0 = acc[mi][ni][rr * 2 + 0] + bias[c];
                float v1 = acc[mi][ni][rr * 2 + 1] + bias[c + 1];
                if (EPI <= 1) {
                    v0 = fmaxf(v0, 0.f);
                    v1 = fmaxf(v1, 0.f);
                    *reinterpret_cast<__half2*>(out16 + (size_t)(m_off + m) * N + c) =
                        __floats2half2_rn(v0, v1);
                } else {
                    int t = g_tok_of_rank[m_off + m];
                    float2 xv = *reinterpret_cast<const float2*>(xres + (size_t)t * C_DIM + c);
                    float2 o;
                    o.x = xv.x + v0;
                    o.y = xv.y + v1;
                    *reinterpret_cast<float2*>(outp + (size_t)t * C_DIM + c) = o;
                }
            }
        }
}

// ---------------- logits + argmax + borderline flagging (1 warp / token) ----------------
__global__ void k_logits(const float* __restrict__ rw2, const float* __restrict__ rb2) {
    int t = blockIdx.x * (blockDim.x >> 5) + (threadIdx.x >> 5);
    if (t >= N_TOK) return;
    int lane = threadIdx.x & 31;
    float s0 = 0.f, s1 = 0.f, s2 = 0.f;
    for (int j = lane; j < RH_DIM; j += 32) {
        float h = __half2float(g_hid[(size_t)t * RH_DIM + j]);
        s0 += h * rw2[j * 3 + 0];
        s1 += h * rw2[j * 3 + 1];
        s2 += h * rw2[j * 3 + 2];
    }
#pragma unroll
    for (int o = 16; o; o >>= 1) {
        s0 += __shfl_xor_sync(0xFFFFFFFFu, s0, o);
        s1 += __shfl_xor_sync(0xFFFFFFFFu, s1, o);
        s2 += __shfl_xor_sync(0xFFFFFFFFu, s2, o);
    }
    if (lane == 0) {
        s0 += rb2[0]; s1 += rb2[1]; s2 += rb2[2];
        int be = 0;
        float bv = s0, sv = -1e30f;
        if (s1 > bv) { sv = bv; bv = s1; be = 1; } else sv = s1;
        if (s2 > bv) { sv = bv; bv = s2; be = 2; } else if (s2 > sv) sv = s2;
        g_expert[t] = be;
        if (bv - sv < ROUTER_TAU) {
            int i = atomicAdd(&g_nflag, 1);
            g_flaglist[i] = t;
        }
    }
}

// ---------------- fp32 exact router recompute for flagged tokens ----------------
__global__ void __launch_bounds__(RH_DIM) k_fixup(
    const float* __restrict__ x, const float* __restrict__ rw1, const float* __restrict__ rb1,
    const float* __restrict__ rw2, const float* __restrict__ rb2)
{
    __shared__ float sx[C_DIM];
    __shared__ float sh[RH_DIM];
    __shared__ float sl[3];
    int nflag = g_nflag;
    for (int it = blockIdx.x; it < nflag; it += gridDim.x) {
        int t = g_flaglist[it];
        __syncthreads();
        for (int cidx = threadIdx.x; cidx < C_DIM; cidx += RH_DIM) sx[cidx] = x[(size_t)t * C_DIM + cidx];
        __syncthreads();
        int j = threadIdx.x;
        float h = rb1[j];
        for (int cidx = 0; cidx < C_DIM; cidx++) h = fmaf(sx[cidx], rw1[cidx * RH_DIM + j], h);
        sh[j] = fmaxf(h, 0.f);
        __syncthreads();
        if (threadIdx.x < 3) {
            int ee = threadIdx.x;
            float s = rb2[ee];
            for (int jj = 0; jj < RH_DIM; jj++) s = fmaf(sh[jj], rw2[jj * 3 + ee], s);
            sl[ee] = s;
        }
        __syncthreads();
        if (threadIdx.x == 0) {
            int be = 0;
            float bv = sl[0];
            if (sl[1] > bv) { bv = sl[1]; be = 1; }
            if (sl[2] > bv) { bv = sl[2]; be = 2; }
            g_expert[t] = be;
        }
    }
}

// ---------------- routing bookkeeping ----------------
__global__ void k_count() {
    int t = blockIdx.x * blockDim.x + threadIdx.x;
    if (t < N_TOK) atomicAdd(&g_cnt[g_expert[t]], 1);
}
__global__ void k_offsets() {
    if (threadIdx.x == 0) {
        g_off[0] = 0;
        for (int e = 0; e < E_NUM; e++) g_off[e + 1] = g_off[e] + g_cnt[e];
    }
}
__global__ void k_rank() {
    int t = blockIdx.x * blockDim.x + threadIdx.x;
    if (t < N_TOK) {
        int e = g_expert[t];
        int r = atomicAdd(&g_pos[e], 1);
        g_tok_of_rank[g_off[e] + r] = t;
    }
}
// gather x16 rows into expert-contiguous xperm (uint4 = 8 halfs)
#define ROW_U4 (C_DIM * 2 / 16)  // 112
__global__ void k_gather() {
    int idx = blockIdx.x * blockDim.x + threadIdx.x;
    if (idx >= N_TOK * ROW_U4) return;
    int r = idx / ROW_U4, c = idx % ROW_U4;
    int t = g_tok_of_rank[r];
    reinterpret_cast<uint4*>(g_xperm)[(size_t)r * ROW_U4 + c] =
        reinterpret_cast<const uint4*>(g_x16)[(size_t)t * ROW_U4 + c];
}

// ---------------- launch ----------------
extern "C" void kernel_launch(void* const* d_in, const int* in_sizes, int n_in,
                              void* d_out, int out_size) {
    const float* x = (const float*)d_in[0];
    const float* rw1 = (const float*)d_in[1];
    const float* rb1 = (const float*)d_in[2];
    const float* rw2 = (const float*)d_in[3];
    const float* rb2 = (const float*)d_in[4];
    const float* eb_in = (const float*)d_in[6];
    const float* ew_in = (const float*)d_in[5];
    const float* ew_out = (const float*)d_in[7];
    const float* eb_out = (const float*)d_in[8];
    float* out = (float*)d_out;

    k_init<<<1, 32>>>();

    int n4x = N_TOK * C_DIM / 4;
    k_cast<0><<<(n4x + 255) / 256, 256>>>((const float4*)x, n4x);
    int n4w1 = C_DIM * RH_DIM / 4;
    k_cast<1><<<(n4w1 + 255) / 256, 256>>>((const float4*)rw1, n4w1);
    int n4wi = E_NUM * C_DIM * H_DIM / 4;
    k_cast<2><<<(n4wi + 255) / 256, 256>>>((const float4*)ew_in, n4wi);
    k_cast<3><<<(n4wi + 255) / 256, 256>>>((const float4*)ew_out, n4wi);

    // router hid = relu(x @ rw1 + rb1)
    dim3 g1(N_TOK / BM, (RH_DIM + BN - 1) / BN, 1);
    k_gemm<0><<<g1, 256>>>(rb1, N_TOK, RH_DIM, C_DIM, nullptr, nullptr);

    k_logits<<<N_TOK / 8, 256>>>(rw2, rb2);
    k_fixup<<<256, RH_DIM>>>(x, rw1, rb1, rw2, rb2);
    k_count<<<N_TOK / 256, 256>>>();
    k_offsets<<<1, 32>>>();
    k_rank<<<N_TOK / 256, 256>>>();
    k_gather<<<(N_TOK * ROW_U4 + 255) / 256, 256>>>();

    // expert GEMM1: h = relu(xperm @ ew_in[e] + eb_in[e])
    dim3 g2(N_TOK / BM, (H_DIM + BN - 1) / BN, E_NUM);
    k_gemm<1><<<g2, 256>>>(eb_in, 0, H_DIM, C_DIM, nullptr, nullptr);

    // expert GEMM2 + residual scatter: out[t] = x[t] + h @ ew_out[e] + eb_out[e]
    dim3 g3(N_TOK / BM, (C_DIM + BN - 1) / BN, E_NUM);
    k_gemm<2><<<g3, 256>>>(eb_out, 0, C_DIM, H_DIM, x, out);

    (void)in_sizes; (void)n_in; (void)out_size;
}

// round 5
// speedup vs baseline: 1.0471x; 1.0471x over previous
#include <cuda_runtime.h>
#include <cuda_fp16.h>
#include <cstdint>

#define N_TOK 16384
#define C_DIM 896
#define RH_DIM 448
#define E_NUM 3
#define H_DIM 3136
#define ROUTER_TAU 2e-3f

#define BM 128
#define BN 128
#define BK 32
#define SAW (BK + 8)     // 40 halfs per A row
#define SBW (BN + 8)     // 136 halfs per B row

// ---------------- scratch ----------------
__device__ __align__(256) __half g_x16[N_TOK * C_DIM];
__device__ __align__(256) __half g_xperm[N_TOK * C_DIM];
__device__ __align__(256) __half g_w1[C_DIM * RH_DIM];                      // [C][RH]
__device__ __align__(256) __half g_win[(size_t)E_NUM * C_DIM * H_DIM];     // [E][C][H]
__device__ __align__(256) __half g_wout[(size_t)E_NUM * H_DIM * C_DIM];    // [E][H][C]
__device__ __align__(256) __half g_hid[N_TOK * RH_DIM];
__device__ __align__(256) __half g_h[(size_t)N_TOK * H_DIM];
__device__ int g_expert[N_TOK];
__device__ int g_tok_of_rank[N_TOK];
__device__ int g_flaglist[N_TOK];
__device__ int g_cnt[E_NUM];
__device__ int g_pos[E_NUM];
__device__ int g_off[E_NUM + 1];
__device__ int g_nflag;

__device__ __forceinline__ unsigned smem_u32(const void* p) {
    return (unsigned)__cvta_generic_to_shared(p);
}

// ---------------- init ----------------
__global__ void k_init() {
    if (threadIdx.x < E_NUM) { g_cnt[threadIdx.x] = 0; g_pos[threadIdx.x] = 0; }
    if (threadIdx.x == 0) g_nflag = 0;
}

// ---------------- fp32 -> fp16 casts ----------------
template <int WHICH>
__global__ void k_cast(const float4* __restrict__ src, int n4) {
    __half2* dst = (WHICH == 0) ? (__half2*)g_x16
                 : (WHICH == 1) ? (__half2*)g_w1
                 : (WHICH == 2) ? (__half2*)g_win
                                : (__half2*)g_wout;
    int i = blockIdx.x * blockDim.x + threadIdx.x;
    if (i < n4) {
        float4 v = src[i];
        dst[2 * i + 0] = __floats2half2_rn(v.x, v.y);
        dst[2 * i + 1] = __floats2half2_rn(v.z, v.w);
    }
}

// ---------------- fp16 GEMM, 128x128x32 tiles, 2-stage cp.async, 64x32 warp tiles --------
// EPI 0: router  A=g_x16   [16384,C], B=g_w1   [C][RH],  relu -> g_hid (fp16)
// EPI 1: expert1 A=g_xperm (grouped), B=g_win[e][C][H],  relu -> g_h   (fp16)
// EPI 2: expert2 A=g_h     (grouped), B=g_wout[e][H][C], +bias+residual -> out fp32 scatter
template <int EPI, int NN, int KK>
__global__ void __launch_bounds__(256, 2) k_gemm(
    const float* __restrict__ bias0,
    const float* __restrict__ xres, float* __restrict__ outp)
{
    constexpr int KT = KK / BK;

    int e = (EPI == 0) ? 0 : blockIdx.z;
    int m_off = 0, M = N_TOK;
    if (EPI != 0) { m_off = g_off[e]; M = g_off[e + 1] - m_off; }
    int m0 = blockIdx.x * BM;
    if (m0 >= M) return;
    int n0 = blockIdx.y * BN;

    const __half* A = ((EPI == 0) ? g_x16 : (EPI == 1) ? g_xperm : g_h) + (size_t)m_off * KK;
    const __half* Bp = ((EPI == 0) ? g_w1 : (EPI == 1) ? g_win : g_wout) + (size_t)e * KK * NN;
    const float* bias = bias0 + (size_t)e * NN;
    __half* out16 = (EPI == 0) ? g_hid : g_h;

    __shared__ __half sA[2][BM][SAW];
    __shared__ __half sB[2][BK][SBW];

    int tid = threadIdx.x, lane = tid & 31, warp = tid >> 5;
    int wm = warp & 1, wn = warp >> 1;  // 2 M-warps x 4 N-warps; warp tile 64x32

    float acc[4][4][4];
#pragma unroll
    for (int i = 0; i < 4; i++)
#pragma unroll
        for (int j = 0; j < 4; j++)
#pragma unroll
            for (int k = 0; k < 4; k++) acc[i][j][k] = 0.f;

    auto load_tile = [&](int kt, int s) {
        int k0 = kt * BK;
#pragma unroll
        for (int i = 0; i < 2; i++) {  // A: 128 rows x 4 chunks
            int q = tid + i * 256;
            int row = q >> 2, c = q & 3;
            int gm = m0 + row;
            const __half* src = A + (size_t)(gm < M ? gm : 0) * KK + k0 + c * 8;
            unsigned dst = smem_u32(&sA[s][row][c * 8]);
            int sz = (gm < M) ? 16 : 0;
            asm volatile("cp.async.cg.shared.global [%0],[%1],16,%2;\n" ::"r"(dst), "l"(src), "r"(sz));
        }
#pragma unroll
        for (int i = 0; i < 2; i++) {  // B: 32 rows x 16 chunks
            int q = tid + i * 256;
            int row = q >> 4, c = q & 15;
            int gn = n0 + c * 8;
            const __half* src = Bp + (size_t)(k0 + row) * NN + (gn < NN ? gn : NN - 8);
            unsigned dst = smem_u32(&sB[s][row][c * 8]);
            int sz = (gn < NN) ? 16 : 0;
            asm volatile("cp.async.cg.shared.global [%0],[%1],16,%2;\n" ::"r"(dst), "l"(src), "r"(sz));
        }
        asm volatile("cp.async.commit_group;\n");
    };

    auto compute_stage = [&](int s) {
        int lrow = lane & 15, lcol = (lane >> 4) * 8;
#pragma unroll
        for (int ks = 0; ks < 2; ks++) {
            unsigned a[4][4], b[2][4];
#pragma unroll
            for (int mi = 0; mi < 4; mi++) {
                unsigned addr = smem_u32(&sA[s][wm * 64 + mi * 16 + lrow][ks * 16 + lcol]);
                asm volatile("ldmatrix.sync.aligned.m8n8.x4.shared.b16 {%0,%1,%2,%3},[%4];\n"
                             : "=r"(a[mi][0]), "=r"(a[mi][1]), "=r"(a[mi][2]), "=r"(a[mi][3])
                             : "r"(addr));
            }
#pragma unroll
            for (int nq = 0; nq < 2; nq++) {
                unsigned addr = smem_u32(&sB[s][ks * 16 + lrow][wn * 32 + nq * 16 + lcol]);
                asm volatile("ldmatrix.sync.aligned.m8n8.x4.trans.shared.b16 {%0,%1,%2,%3},[%4];\n"
                             : "=r"(b[nq][0]), "=r"(b[nq][1]), "=r"(b[nq][2]), "=r"(b[nq][3])
                             : "r"(addr));
            }
#pragma unroll
            for (int mi = 0; mi < 4; mi++)
#pragma unroll
                for (int ni = 0; ni < 4; ni++) {
                    unsigned b0 = b[ni >> 1][(ni & 1) * 2], b1 = b[ni >> 1][(ni & 1) * 2 + 1];
                    asm volatile(
                        "mma.sync.aligned.m16n8k16.row.col.f32.f16.f16.f32 "
                        "{%0,%1,%2,%3},{%4,%5,%6,%7},{%8,%9},{%0,%1,%2,%3};\n"
                        : "+f"(acc[mi][ni][0]), "+f"(acc[mi][ni][1]),
                          "+f"(acc[mi][ni][2]), "+f"(acc[mi][ni][3])
                        : "r"(a[mi][0]), "r"(a[mi][1]), "r"(a[mi][2]), "r"(a[mi][3]),
                          "r"(b0), "r"(b1));
                }
        }
    };

    load_tile(0, 0);
    int buf = 0;
    for (int kt = 0; kt < KT; kt++) {
        if (kt + 1 < KT) {
            load_tile(kt + 1, buf ^ 1);
            asm volatile("cp.async.wait_group 1;\n");
        } else {
            asm volatile("cp.async.wait_group 0;\n");
        }
        __syncthreads();
        compute_stage(buf);
        buf ^= 1;
        __syncthreads();
    }

    // ---- epilogue ----
#pragma unroll
    for (int mi = 0; mi < 4; mi++)
#pragma unroll
        for (int ni = 0; ni < 4; ni++) {
            int r0 = wm * 64 + mi * 16 + (lane >> 2);
            int c = n0 + wn * 32 + ni * 8 + (lane & 3) * 2;
            if (c >= NN) continue;
#pragma unroll
            for (int rr = 0; rr < 2; rr++) {
                int m = m0 + r0 + rr * 8;
                if (m >= M) continue;
                float v0 = acc[mi][ni][rr * 2 + 0] + bias[c];
                float v1 = acc[mi][ni][rr * 2 + 1] + bias[c + 1];
                if (EPI <= 1) {
                    v0 = fmaxf(v0, 0.f);
                    v1 = fmaxf(v1, 0.f);
                    *reinterpret_cast<__half2*>(out16 + (size_t)(m_off + m) * NN + c) =
                        __floats2half2_rn(v0, v1);
                } else {
                    int t = g_tok_of_rank[m_off + m];
                    float2 xv = *reinterpret_cast<const float2*>(xres + (size_t)t * C_DIM + c);
                    float2 o;
                    o.x = xv.x + v0;
                    o.y = xv.y + v1;
                    *reinterpret_cast<float2*>(outp + (size_t)t * C_DIM + c) = o;
                }
            }
        }
}

// ---------------- logits + argmax + flagging + count ----------------
__global__ void k_logits(const float* __restrict__ rw2, const float* __restrict__ rb2) {
    int t = blockIdx.x * (blockDim.x >> 5) + (threadIdx.x >> 5);
    if (t >= N_TOK) return;
    int lane = threadIdx.x & 31;
    float s0 = 0.f, s1 = 0.f, s2 = 0.f;
    for (int j = lane; j < RH_DIM; j += 32) {
        float h = __half2float(g_hid[(size_t)t * RH_DIM + j]);
        s0 += h * rw2[j * 3 + 0];
        s1 += h * rw2[j * 3 + 1];
        s2 += h * rw2[j * 3 + 2];
    }
#pragma unroll
    for (int o = 16; o; o >>= 1) {
        s0 += __shfl_xor_sync(0xFFFFFFFFu, s0, o);
        s1 += __shfl_xor_sync(0xFFFFFFFFu, s1, o);
        s2 += __shfl_xor_sync(0xFFFFFFFFu, s2, o);
    }
    if (lane == 0) {
        s0 += rb2[0]; s1 += rb2[1]; s2 += rb2[2];
        int be = 0;
        float bv = s0, sv = -1e30f;
        if (s1 > bv) { sv = bv; bv = s1; be = 1; } else sv = s1;
        if (s2 > bv) { sv = bv; bv = s2; be = 2; } else if (s2 > sv) sv = s2;
        g_expert[t] = be;
        atomicAdd(&g_cnt[be], 1);
        if (bv - sv < ROUTER_TAU) {
            int i = atomicAdd(&g_nflag, 1);
            g_flaglist[i] = t;
        }
    }
}

// ---------------- fp32 exact router recompute for flagged tokens ----------------
__global__ void __launch_bounds__(RH_DIM) k_fixup(
    const float* __restrict__ x, const float* __restrict__ rw1, const float* __restrict__ rb1,
    const float* __restrict__ rw2, const float* __restrict__ rb2)
{
    __shared__ float sx[C_DIM];
    __shared__ float sh[RH_DIM];
    __shared__ float sl[3];
    int nflag = g_nflag;
    for (int it = blockIdx.x; it < nflag; it += gridDim.x) {
        int t = g_flaglist[it];
        __syncthreads();
        for (int c = threadIdx.x; c < C_DIM; c += RH_DIM) sx[c] = x[(size_t)t * C_DIM + c];
        __syncthreads();
        int j = threadIdx.x;
        float h = rb1[j];
        for (int c = 0; c < C_DIM; c++) h = fmaf(sx[c], rw1[c * RH_DIM + j], h);
        sh[j] = fmaxf(h, 0.f);
        __syncthreads();
        if (threadIdx.x < 3) {
            int ee = threadIdx.x;
            float s = rb2[ee];
            for (int jj = 0; jj < RH_DIM; jj++) s = fmaf(sh[jj], rw2[jj * 3 + ee], s);
            sl[ee] = s;
        }
        __syncthreads();
        if (threadIdx.x == 0) {
            int be = 0;
            float bv = sl[0];
            if (sl[1] > bv) { bv = sl[1]; be = 1; }
            if (sl[2] > bv) { bv = sl[2]; be = 2; }
            int old = g_expert[t];
            if (be != old) {
                g_expert[t] = be;
                atomicSub(&g_cnt[old], 1);
                atomicAdd(&g_cnt[be], 1);
            }
        }
    }
}

// ---------------- routing bookkeeping ----------------
__global__ void k_offsets() {
    if (threadIdx.x == 0) {
        g_off[0] = 0;
        for (int e = 0; e < E_NUM; e++) g_off[e + 1] = g_off[e] + g_cnt[e];
    }
}
__global__ void k_rank() {
    int t = blockIdx.x * blockDim.x + threadIdx.x;
    if (t < N_TOK) {
        int e = g_expert[t];
        int r = atomicAdd(&g_pos[e], 1);
        g_tok_of_rank[g_off[e] + r] = t;
    }
}
#define ROW_U4 (C_DIM * 2 / 16)  // 112
__global__ void k_gather() {
    int idx = blockIdx.x * blockDim.x + threadIdx.x;
    if (idx >= N_TOK * ROW_U4) return;
    int r = idx / ROW_U4, c = idx % ROW_U4;
    int t = g_tok_of_rank[r];
    reinterpret_cast<uint4*>(g_xperm)[(size_t)r * ROW_U4 + c] =
        reinterpret_cast<const uint4*>(g_x16)[(size_t)t * ROW_U4 + c];
}

// ---------------- launch ----------------
extern "C" void kernel_launch(void* const* d_in, const int* in_sizes, int n_in,
                              void* d_out, int out_size) {
    const float* x = (const float*)d_in[0];
    const float* rw1 = (const float*)d_in[1];
    const float* rb1 = (const float*)d_in[2];
    const float* rw2 = (const float*)d_in[3];
    const float* rb2 = (const float*)d_in[4];
    const float* ew_in = (const float*)d_in[5];
    const float* eb_in = (const float*)d_in[6];
    const float* ew_out = (const float*)d_in[7];
    const float* eb_out = (const float*)d_in[8];
    float* out = (float*)d_out;

    k_init<<<1, 32>>>();

    int n4x = N_TOK * C_DIM / 4;
    k_cast<0><<<(n4x + 255) / 256, 256>>>((const float4*)x, n4x);
    int n4w1 = C_DIM * RH_DIM / 4;
    k_cast<1><<<(n4w1 + 255) / 256, 256>>>((const float4*)rw1, n4w1);
    int n4wi = E_NUM * C_DIM * H_DIM / 4;
    k_cast<2><<<(n4wi + 255) / 256, 256>>>((const float4*)ew_in, n4wi);
    k_cast<3><<<(n4wi + 255) / 256, 256>>>((const float4*)ew_out, n4wi);

    // router: g_hid = relu(x @ rw1 + rb1)
    dim3 g1(N_TOK / BM, (RH_DIM + BN - 1) / BN, 1);
    k_gemm<0, RH_DIM, C_DIM><<<g1, 256>>>(rb1, nullptr, nullptr);

    k_logits<<<N_TOK / 8, 256>>>(rw2, rb2);
    k_fixup<<<256, RH_DIM>>>(x, rw1, rb1, rw2, rb2);
    k_offsets<<<1, 32>>>();
    k_rank<<<N_TOK / 256, 256>>>();
    k_gather<<<(N_TOK * ROW_U4 + 255) / 256, 256>>>();

    // expert GEMM1: g_h = relu(xperm @ ew_in[e] + eb_in[e])
    dim3 g2(N_TOK / BM, (H_DIM + BN - 1) / BN, E_NUM);
    k_gemm<1, H_DIM, C_DIM><<<g2, 256>>>(eb_in, nullptr, nullptr);

    // expert GEMM2 + residual scatter
    dim3 g3(N_TOK / BM, (C_DIM + BN - 1) / BN, E_NUM);
    k_gemm<2, C_DIM, H_DIM><<<g3, 256>>>(eb_out, x, out);

    (void)in_sizes; (void)n_in; (void)out_size;
}

// round 8
// speedup vs baseline: 1.0493x; 1.0021x over previous
#include <cuda_runtime.h>
#include <cuda_fp16.h>
#include <cstdint>

#define N_TOK 16384
#define C_DIM 896
#define RH_DIM 448
#define E_NUM 3
#define H_DIM 3136
#define ROUTER_TAU 2e-3f

#define BM 128
#define BN 128
#define BK 32
#define SAW (BK + 8)     // 40 halfs per A row
#define SBW (BN + 8)     // 136 halfs per B row

// ---------------- scratch ----------------
__device__ __align__(256) __half g_x16[N_TOK * C_DIM];
__device__ __align__(256) __half g_w1[C_DIM * RH_DIM];                      // [C][RH]
__device__ __align__(256) __half g_win[(size_t)E_NUM * C_DIM * H_DIM];     // [E][C][H]
__device__ __align__(256) __half g_wout[(size_t)E_NUM * H_DIM * C_DIM];    // [E][H][C]
__device__ __align__(256) __half g_hid[N_TOK * RH_DIM];
__device__ __align__(256) __half g_h[(size_t)N_TOK * H_DIM];
__device__ int g_expert[N_TOK];
__device__ int g_tok_of_rank[N_TOK];
__device__ int g_flaglist[N_TOK];
__device__ int g_cnt[E_NUM];
__device__ int g_pos[E_NUM];
__device__ int g_off[E_NUM + 1];
__device__ int g_nflag;

__device__ __forceinline__ unsigned smem_u32(const void* p) {
    return (unsigned)__cvta_generic_to_shared(p);
}

// ---------------- init ----------------
__global__ void k_init() {
    if (threadIdx.x < E_NUM) { g_cnt[threadIdx.x] = 0; g_pos[threadIdx.x] = 0; }
    if (threadIdx.x == 0) g_nflag = 0;
}

// ---------------- fp32 -> fp16 casts (2 x float4 per thread) ----------------
template <int WHICH>
__global__ void k_cast(const float4* __restrict__ src, int n4) {
    __half2* dst = (WHICH == 0) ? (__half2*)g_x16
                 : (WHICH == 1) ? (__half2*)g_w1
                 : (WHICH == 2) ? (__half2*)g_win
                                : (__half2*)g_wout;
    int i = 2 * (blockIdx.x * blockDim.x + threadIdx.x);
#pragma unroll
    for (int u = 0; u < 2; u++, i++) {
        if (i < n4) {
            float4 v = src[i];
            dst[2 * i + 0] = __floats2half2_rn(v.x, v.y);
            dst[2 * i + 1] = __floats2half2_rn(v.z, v.w);
        }
    }
}

// ---------------- fp16 GEMM, 128x128x32 tiles, 2-stage cp.async, 64x32 warp tiles --------
// EPI 0: router  A=g_x16   [16384,C],          B=g_w1   [C][RH],  relu -> g_hid (fp16)
// EPI 1: expert1 A=g_x16 rows via tok_of_rank, B=g_win[e][C][H],  relu -> g_h   (fp16, rank order)
// EPI 2: expert2 A=g_h     (grouped),          B=g_wout[e][H][C], +bias+residual -> out fp32 scatter
template <int EPI, int NN, int KK>
__global__ void __launch_bounds__(256, 2) k_gemm(
    const float* __restrict__ bias0,
    const float* __restrict__ xres, float* __restrict__ outp)
{
    constexpr int KT = KK / BK;

    int e = (EPI == 0) ? 0 : blockIdx.z;
    int m_off = 0, M = N_TOK;
    if (EPI != 0) { m_off = g_off[e]; M = g_off[e + 1] - m_off; }
    int m0 = blockIdx.x * BM;
    if (m0 >= M) return;
    int n0 = blockIdx.y * BN;

    const __half* A = ((EPI == 2) ? g_h : g_x16) + (size_t)m_off * KK;  // EPI1 ignores this base
    const __half* Bp = ((EPI == 0) ? g_w1 : (EPI == 1) ? g_win : g_wout) + (size_t)e * KK * NN;
    const float* bias = bias0 + (size_t)e * NN;
    __half* out16 = (EPI == 0) ? g_hid : g_h;

    __shared__ __half sA[2][BM][SAW];
    __shared__ __half sB[2][BK][SBW];

    int tid = threadIdx.x, lane = tid & 31, warp = tid >> 5;
    int wm = warp & 1, wn = warp >> 1;  // 2 M-warps x 4 N-warps; warp tile 64x32

    float acc[4][4][4];
#pragma unroll
    for (int i = 0; i < 4; i++)
#pragma unroll
        for (int j = 0; j < 4; j++)
#pragma unroll
            for (int k = 0; k < 4; k++) acc[i][j][k] = 0.f;

    auto load_tile = [&](int kt, int s) {
        int k0 = kt * BK;
#pragma unroll
        for (int i = 0; i < 2; i++) {  // A: 128 rows x 4 chunks
            int q = tid + i * 256;
            int row = q >> 2, c = q & 3;
            int gm = m0 + row;
            const __half* src;
            if (EPI == 1) {
                int tok = (gm < M) ? g_tok_of_rank[m_off + gm] : 0;
                src = g_x16 + (size_t)tok * KK + k0 + c * 8;
            } else {
                src = A + (size_t)(gm < M ? gm : 0) * KK + k0 + c * 8;
            }
            unsigned dst = smem_u32(&sA[s][row][c * 8]);
            int sz = (gm < M) ? 16 : 0;
            asm volatile("cp.async.cg.shared.global [%0],[%1],16,%2;\n" ::"r"(dst), "l"(src), "r"(sz));
        }
#pragma unroll
        for (int i = 0; i < 2; i++) {  // B: 32 rows x 16 chunks
            int q = tid + i * 256;
            int row = q >> 4, c = q & 15;
            int gn = n0 + c * 8;
            const __half* src = Bp + (size_t)(k0 + row) * NN + (gn < NN ? gn : NN - 8);
            unsigned dst = smem_u32(&sB[s][row][c * 8]);
            int sz = (gn < NN) ? 16 : 0;
            asm volatile("cp.async.cg.shared.global [%0],[%1],16,%2;\n" ::"r"(dst), "l"(src), "r"(sz));
        }
        asm volatile("cp.async.commit_group;\n");
    };

    auto compute_stage = [&](int s) {
        int lrow = lane & 15, lcol = (lane >> 4) * 8;
#pragma unroll
        for (int ks = 0; ks < 2; ks++) {
            unsigned a[4][4], b[2][4];
#pragma unroll
            for (int mi = 0; mi < 4; mi++) {
                unsigned addr = smem_u32(&sA[s][wm * 64 + mi * 16 + lrow][ks * 16 + lcol]);
                asm volatile("ldmatrix.sync.aligned.m8n8.x4.shared.b16 {%0,%1,%2,%3},[%4];\n"
                             : "=r"(a[mi][0]), "=r"(a[mi][1]), "=r"(a[mi][2]), "=r"(a[mi][3])
                             : "r"(addr));
            }
#pragma unroll
            for (int nq = 0; nq < 2; nq++) {
                unsigned addr = smem_u32(&sB[s][ks * 16 + lrow][wn * 32 + nq * 16 + lcol]);
                asm volatile("ldmatrix.sync.aligned.m8n8.x4.trans.shared.b16 {%0,%1,%2,%3},[%4];\n"
                             : "=r"(b[nq][0]), "=r"(b[nq][1]), "=r"(b[nq][2]), "=r"(b[nq][3])
                             : "r"(addr));
            }
#pragma unroll
            for (int mi = 0; mi < 4; mi++)
#pragma unroll
                for (int ni = 0; ni < 4; ni++) {
                    unsigned b0 = b[ni >> 1][(ni & 1) * 2], b1 = b[ni >> 1][(ni & 1) * 2 + 1];
                    asm volatile(
                        "mma.sync.aligned.m16n8k16.row.col.f32.f16.f16.f32 "
                        "{%0,%1,%2,%3},{%4,%5,%6,%7},{%8,%9},{%0,%1,%2,%3};\n"
                        : "+f"(acc[mi][ni][0]), "+f"(acc[mi][ni][1]),
                          "+f"(acc[mi][ni][2]), "+f"(acc[mi][ni][3])
                        : "r"(a[mi][0]), "r"(a[mi][1]), "r"(a[mi][2]), "r"(a[mi][3]),
                          "r"(b0), "r"(b1));
                }
        }
    };

    load_tile(0, 0);
    int buf = 0;
    for (int kt = 0; kt < KT; kt++) {
        if (kt + 1 < KT) {
            load_tile(kt + 1, buf ^ 1);
            asm volatile("cp.async.wait_group 1;\n");
        } else {
            asm volatile("cp.async.wait_group 0;\n");
        }
        __syncthreads();
        compute_stage(buf);
        buf ^= 1;
        __syncthreads();
    }

    // ---- epilogue ----
#pragma unroll
    for (int mi = 0; mi < 4; mi++)
#pragma unroll
        for (int ni = 0; ni < 4; ni++) {
            int r0 = wm * 64 + mi * 16 + (lane >> 2);
            int c = n0 + wn * 32 + ni * 8 + (lane & 3) * 2;
            if (c >= NN) continue;
#pragma unroll
            for (int rr = 0; rr < 2; rr++) {
                int m = m0 + r0 + rr * 8;
                if (m >= M) continue;
                float v0 = acc[mi][ni][rr * 2 + 0] + bias[c];
                float v1 = acc[mi][ni][rr * 2 + 1] + bias[c + 1];
                if (EPI <= 1) {
                    v0 = fmaxf(v0, 0.f);
                    v1 = fmaxf(v1, 0.f);
                    *reinterpret_cast<__half2*>(out16 + (size_t)(m_off + m) * NN + c) =
                        __floats2half2_rn(v0, v1);
                } else {
                    int t = g_tok_of_rank[m_off + m];
                    float2 xv = *reinterpret_cast<const float2*>(xres + (size_t)t * C_DIM + c);
                    float2 o;
                    o.x = xv.x + v0;
                    o.y = xv.y + v1;
                    *reinterpret_cast<float2*>(outp + (size_t)t * C_DIM + c) = o;
                }
            }
        }
}

// ---------------- logits + argmax + flagging + count ----------------
__global__ void k_logits(const float* __restrict__ rw2, const float* __restrict__ rb2) {
    int t = blockIdx.x * (blockDim.x >> 5) + (threadIdx.x >> 5);
    if (t >= N_TOK) return;
    int lane = threadIdx.x & 31;
    float s0 = 0.f, s1 = 0.f, s2 = 0.f;
    for (int j = lane; j < RH_DIM; j += 32) {
        float h = __half2float(g_hid[(size_t)t * RH_DIM + j]);
        s0 += h * rw2[j * 3 + 0];
        s1 += h * rw2[j * 3 + 1];
        s2 += h * rw2[j * 3 + 2];
    }
#pragma unroll
    for (int o = 16; o; o >>= 1) {
        s0 += __shfl_xor_sync(0xFFFFFFFFu, s0, o);
        s1 += __shfl_xor_sync(0xFFFFFFFFu, s1, o);
        s2 += __shfl_xor_sync(0xFFFFFFFFu, s2, o);
    }
    if (lane == 0) {
        s0 += rb2[0]; s1 += rb2[1]; s2 += rb2[2];
        int be = 0;
        float bv = s0, sv = -1e30f;
        if (s1 > bv) { sv = bv; bv = s1; be = 1; } else sv = s1;
        if (s2 > bv) { sv = bv; bv = s2; be = 2; } else if (s2 > sv) sv = s2;
        g_expert[t] = be;
        atomicAdd(&g_cnt[be], 1);
        if (bv - sv < ROUTER_TAU) {
            int i = atomicAdd(&g_nflag, 1);
            g_flaglist[i] = t;
        }
    }
}

// ---------------- fp32 exact router recompute for flagged tokens ----------------
__global__ void __launch_bounds__(RH_DIM) k_fixup(
    const float* __restrict__ x, const float* __restrict__ rw1, const float* __restrict__ rb1,
    const float* __restrict__ rw2, const float* __restrict__ rb2)
{
    __shared__ float sx[C_DIM];
    __shared__ float sh[RH_DIM];
    __shared__ float sl[3];
    int nflag = g_nflag;
    for (int it = blockIdx.x; it < nflag; it += gridDim.x) {
        int t = g_flaglist[it];
        __syncthreads();
        for (int c = threadIdx.x; c < C_DIM; c += RH_DIM) sx[c] = x[(size_t)t * C_DIM + c];
        __syncthreads();
        int j = threadIdx.x;
        float h = rb1[j];
        for (int c = 0; c < C_DIM; c++) h = fmaf(sx[c], rw1[c * RH_DIM + j], h);
        sh[j] = fmaxf(h, 0.f);
        __syncthreads();
        if (threadIdx.x < 3) {
            int ee = threadIdx.x;
            float s = rb2[ee];
            for (int jj = 0; jj < RH_DIM; jj++) s = fmaf(sh[jj], rw2[jj * 3 + ee], s);
            sl[ee] = s;
        }
        __syncthreads();
        if (threadIdx.x == 0) {
            int be = 0;
            float bv = sl[0];
            if (sl[1] > bv) { bv = sl[1]; be = 1; }
            if (sl[2] > bv) { bv = sl[2]; be = 2; }
            int old = g_expert[t];
            if (be != old) {
                g_expert[t] = be;
                atomicSub(&g_cnt[old], 1);
                atomicAdd(&g_cnt[be], 1);
            }
        }
    }
}

// ---------------- routing bookkeeping ----------------
__global__ void k_offsets() {
    if (threadIdx.x == 0) {
        g_off[0] = 0;
        for (int e = 0; e < E_NUM; e++) g_off[e + 1] = g_off[e] + g_cnt[e];
    }
}
__global__ void k_rank() {
    int t = blockIdx.x * blockDim.x + threadIdx.x;
    if (t < N_TOK) {
        int e = g_expert[t];
        int r = atomicAdd(&g_pos[e], 1);
        g_tok_of_rank[g_off[e] + r] = t;
    }
}

// ---------------- launch ----------------
extern "C" void kernel_launch(void* const* d_in, const int* in_sizes, int n_in,
                              void* d_out, int out_size) {
    const float* x = (const float*)d_in[0];
    const float* rw1 = (const float*)d_in[1];
    const float* rb1 = (const float*)d_in[2];
    const float* rw2 = (const float*)d_in[3];
    const float* rb2 = (const float*)d_in[4];
    const float* ew_in = (const float*)d_in[5];
    const float* eb_in = (const float*)d_in[6];
    const float* ew_out = (const float*)d_in[7];
    const float* eb_out = (const float*)d_in[8];
    float* out = (float*)d_out;

    k_init<<<1, 32>>>();

    int n4x = N_TOK * C_DIM / 4;
    k_cast<0><<<(n4x / 2 + 255) / 256, 256>>>((const float4*)x, n4x);
    int n4w1 = C_DIM * RH_DIM / 4;
    k_cast<1><<<(n4w1 / 2 + 255) / 256, 256>>>((const float4*)rw1, n4w1);
    int n4wi = E_NUM * C_DIM * H_DIM / 4;
    k_cast<2><<<(n4wi / 2 + 255) / 256, 256>>>((const float4*)ew_in, n4wi);
    k_cast<3><<<(n4wi / 2 + 255) / 256, 256>>>((const float4*)ew_out, n4wi);

    // router: g_hid = relu(x @ rw1 + rb1)
    dim3 g1(N_TOK / BM, (RH_DIM + BN - 1) / BN, 1);
    k_gemm<0, RH_DIM, C_DIM><<<g1, 256>>>(rb1, nullptr, nullptr);

    k_logits<<<N_TOK / 8, 256>>>(rw2, rb2);
    k_fixup<<<256, RH_DIM>>>(x, rw1, rb1, rw2, rb2);
    k_offsets<<<1, 32>>>();
    k_rank<<<N_TOK / 256, 256>>>();

    // expert GEMM1 (gathers A rows via tok_of_rank): g_h = relu(x16[tok] @ ew_in[e] + eb_in[e])
    dim3 g2(N_TOK / BM, (H_DIM + BN - 1) / BN, E_NUM);
    k_gemm<1, H_DIM, C_DIM><<<g2, 256>>>(eb_in, nullptr, nullptr);

    // expert GEMM2 + residual scatter
    dim3 g3(N_TOK / BM, (C_DIM + BN - 1) / BN, E_NUM);
    k_gemm<2, C_DIM, H_DIM><<<g3, 256>>>(eb_out, x, out);

    (void)in_sizes; (void)n_in; (void)out_size;
}

// round 10
// speedup vs baseline: 1.1368x; 1.0833x over previous
#include <cuda_runtime.h>
#include <cuda_fp16.h>
#include <cstdint>

#define N_TOK 16384
#define C_DIM 896
#define RH_DIM 448
#define E_NUM 3
#define H_DIM 3136
#define ROUTER_TAU 2e-3f

#define BM 128
#define BN 128
#define BK 32
#define NST 3

// ---------------- scratch ----------------
__device__ __align__(256) __half g_x16[N_TOK * C_DIM];
__device__ __align__(256) __half g_w1[C_DIM * RH_DIM];                      // [C][RH]
__device__ __align__(256) __half g_win[(size_t)E_NUM * C_DIM * H_DIM];     // [E][C][H]
__device__ __align__(256) __half g_wout[(size_t)E_NUM * H_DIM * C_DIM];    // [E][H][C]
__device__ __align__(256) __half g_hid[N_TOK * RH_DIM];
__device__ __align__(256) __half g_h[(size_t)N_TOK * H_DIM];
__device__ int g_expert[N_TOK];
__device__ int g_tok_of_rank[N_TOK];
__device__ int g_flaglist[N_TOK];
__device__ int g_cnt[E_NUM];
__device__ int g_pos[E_NUM];
__device__ int g_off[E_NUM + 1];
__device__ int g_nflag;

__device__ __forceinline__ unsigned smem_u32(const void* p) {
    return (unsigned)__cvta_generic_to_shared(p);
}

// ---------------- init ----------------
__global__ void k_init() {
    if (threadIdx.x < E_NUM) { g_cnt[threadIdx.x] = 0; g_pos[threadIdx.x] = 0; }
    if (threadIdx.x == 0) g_nflag = 0;
}

// ---------------- fp32 -> fp16 casts (2 x float4 per thread) ----------------
template <int WHICH>
__global__ void k_cast(const float4* __restrict__ src, int n4) {
    __half2* dst = (WHICH == 0) ? (__half2*)g_x16
                 : (WHICH == 1) ? (__half2*)g_w1
                 : (WHICH == 2) ? (__half2*)g_win
                                : (__half2*)g_wout;
    int i = 2 * (blockIdx.x * blockDim.x + threadIdx.x);
#pragma unroll
    for (int u = 0; u < 2; u++, i++) {
        if (i < n4) {
            float4 v = src[i];
            dst[2 * i + 0] = __floats2half2_rn(v.x, v.y);
            dst[2 * i + 1] = __floats2half2_rn(v.z, v.w);
        }
    }
}

// ---------------- fp16 GEMM, 128x128x32 tiles, 3-stage ring, 1 barrier/slice ------------
// A smem: [128][32] halfs swizzled: 16B chunk c in [0,4), phys = c ^ ((row>>1)&3)
// B smem: [32][128] halfs swizzled: 16B chunk c in [0,16), phys = c ^ (row&7)
// EPI 0: router  A=g_x16   [16384,C],          B=g_w1   [C][RH],  relu -> g_hid (fp16)
// EPI 1: expert1 A=g_x16 rows via tok_of_rank, B=g_win[e][C][H],  relu -> g_h   (rank order)
// EPI 2: expert2 A=g_h     (grouped),          B=g_wout[e][H][C], +bias+residual -> out fp32
template <int EPI, int NN, int KK>
__global__ void __launch_bounds__(256, 2) k_gemm(
    const float* __restrict__ bias0,
    const float* __restrict__ xres, float* __restrict__ outp)
{
    constexpr int KT = KK / BK;

    int e = (EPI == 0) ? 0 : blockIdx.z;
    int m_off = 0, M = N_TOK;
    if (EPI != 0) { m_off = g_off[e]; M = g_off[e + 1] - m_off; }
    int m0 = blockIdx.x * BM;
    if (m0 >= M) return;
    int n0 = blockIdx.y * BN;

    const __half* A = ((EPI == 2) ? g_h : g_x16) + (size_t)m_off * KK;  // EPI1 ignores this base
    const __half* Bp = ((EPI == 0) ? g_w1 : (EPI == 1) ? g_win : g_wout) + (size_t)e * KK * NN;
    const float* bias = bias0 + (size_t)e * NN;
    __half* out16 = (EPI == 0) ? g_hid : g_h;

    __shared__ __half sA[NST][BM][BK];   // 3 x 8192 B
    __shared__ __half sB[NST][BK][BN];   // 3 x 8192 B  -> 49152 B total

    int tid = threadIdx.x, lane = tid & 31, warp = tid >> 5;
    int wm = warp & 1, wn = warp >> 1;  // 2 M-warps x 4 N-warps; warp tile 64x32

    float acc[4][4][4];
#pragma unroll
    for (int i = 0; i < 4; i++)
#pragma unroll
        for (int j = 0; j < 4; j++)
#pragma unroll
            for (int k = 0; k < 4; k++) acc[i][j][k] = 0.f;

    unsigned aBase0 = smem_u32(&sA[0][0][0]);
    unsigned bBase0 = smem_u32(&sB[0][0][0]);

    auto load_tile = [&](int kt, int s) {
        int k0 = kt * BK;
        unsigned aS = aBase0 + s * (BM * BK * 2);
        unsigned bS = bBase0 + s * (BK * BN * 2);
#pragma unroll
        for (int i = 0; i < 2; i++) {  // A: 128 rows x 4 chunks = 512 writes
            int q = tid + i * 256;
            int row = q >> 2, c = q & 3;
            int gm = m0 + row;
            const __half* src;
            if (EPI == 1) {
                int tok = (gm < M) ? g_tok_of_rank[m_off + gm] : 0;
                src = g_x16 + (size_t)tok * KK + k0 + c * 8;
            } else {
                src = A + (size_t)(gm < M ? gm : 0) * KK + k0 + c * 8;
            }
            unsigned dst = aS + row * 64 + ((c ^ ((row >> 1) & 3)) << 4);
            int sz = (gm < M) ? 16 : 0;
            asm volatile("cp.async.cg.shared.global [%0],[%1],16,%2;\n" ::"r"(dst), "l"(src), "r"(sz));
        }
#pragma unroll
        for (int i = 0; i < 2; i++) {  // B: 32 rows x 16 chunks = 512 writes
            int q = tid + i * 256;
            int row = q >> 4, c = q & 15;
            int gn = n0 + c * 8;
            const __half* src = Bp + (size_t)(k0 + row) * NN + (gn < NN ? gn : NN - 8);
            unsigned dst = bS + row * 256 + ((c ^ (row & 7)) << 4);
            int sz = (gn < NN) ? 16 : 0;
            asm volatile("cp.async.cg.shared.global [%0],[%1],16,%2;\n" ::"r"(dst), "l"(src), "r"(sz));
        }
        asm volatile("cp.async.commit_group;\n");
    };

    auto compute_stage = [&](int s) {
        unsigned aS = aBase0 + s * (BM * BK * 2);
        unsigned bS = bBase0 + s * (BK * BN * 2);
        int lrow = lane & 15, lsel = lane >> 4;
#pragma unroll
        for (int ks = 0; ks < 2; ks++) {
            unsigned a[4][4], b[2][4];
#pragma unroll
            for (int mi = 0; mi < 4; mi++) {
                int r = wm * 64 + mi * 16 + lrow;
                int c = ks * 2 + lsel;
                unsigned addr = aS + r * 64 + ((c ^ ((r >> 1) & 3)) << 4);
                asm volatile("ldmatrix.sync.aligned.m8n8.x4.shared.b16 {%0,%1,%2,%3},[%4];\n"
                             : "=r"(a[mi][0]), "=r"(a[mi][1]), "=r"(a[mi][2]), "=r"(a[mi][3])
                             : "r"(addr));
            }
#pragma unroll
            for (int nq = 0; nq < 2; nq++) {
                int r = ks * 16 + lrow;
                int c = wn * 4 + nq * 2 + lsel;
                unsigned addr = bS + r * 256 + ((c ^ (r & 7)) << 4);
                asm volatile("ldmatrix.sync.aligned.m8n8.x4.trans.shared.b16 {%0,%1,%2,%3},[%4];\n"
                             : "=r"(b[nq][0]), "=r"(b[nq][1]), "=r"(b[nq][2]), "=r"(b[nq][3])
                             : "r"(addr));
            }
#pragma unroll
            for (int mi = 0; mi < 4; mi++)
#pragma unroll
                for (int ni = 0; ni < 4; ni++) {
                    unsigned b0 = b[ni >> 1][(ni & 1) * 2], b1 = b[ni >> 1][(ni & 1) * 2 + 1];
                    asm volatile(
                        "mma.sync.aligned.m16n8k16.row.col.f32.f16.f16.f32 "
                        "{%0,%1,%2,%3},{%4,%5,%6,%7},{%8,%9},{%0,%1,%2,%3};\n"
                        : "+f"(acc[mi][ni][0]), "+f"(acc[mi][ni][1]),
                          "+f"(acc[mi][ni][2]), "+f"(acc[mi][ni][3])
                        : "r"(a[mi][0]), "r"(a[mi][1]), "r"(a[mi][2]), "r"(a[mi][3]),
                          "r"(b0), "r"(b1));
                }
        }
    };

    // 3-stage ring, single barrier per K-slice
    load_tile(0, 0);
    load_tile(1, 1);
    for (int kt = 0; kt < KT; kt++) {
        if (kt + 1 < KT) asm volatile("cp.async.wait_group 1;\n");
        else             asm volatile("cp.async.wait_group 0;\n");
        __syncthreads();
        if (kt + 2 < KT) load_tile(kt + 2, (kt + 2) % NST);
        compute_stage(kt % NST);
    }

    // ---- epilogue ----
#pragma unroll
    for (int mi = 0; mi < 4; mi++)
#pragma unroll
        for (int ni = 0; ni < 4; ni++) {
            int r0 = wm * 64 + mi * 16 + (lane >> 2);
            int c = n0 + wn * 32 + ni * 8 + (lane & 3) * 2;
            if (c >= NN) continue;
#pragma unroll
            for (int rr = 0; rr < 2; rr++) {
                int m = m0 + r0 + rr * 8;
                if (m >= M) continue;
                float v0 = acc[mi][ni][rr * 2 + 0] + bias[c];
                float v1 = acc[mi][ni][rr * 2 + 1] + bias[c + 1];
                if (EPI <= 1) {
                    v0 = fmaxf(v0, 0.f);
                    v1 = fmaxf(v1, 0.f);
                    *reinterpret_cast<__half2*>(out16 + (size_t)(m_off + m) * NN + c) =
                        __floats2half2_rn(v0, v1);
                } else {
                    int t = g_tok_of_rank[m_off + m];
                    float2 xv = *reinterpret_cast<const float2*>(xres + (size_t)t * C_DIM + c);
                    float2 o;
                    o.x = xv.x + v0;
                    o.y = xv.y + v1;
                    *reinterpret_cast<float2*>(outp + (size_t)t * C_DIM + c) = o;
                }
            }
        }
}

// ---------------- logits + argmax + flagging + count ----------------
__global__ void k_logits(const float* __restrict__ rw2, const float* __restrict__ rb2) {
    int t = blockIdx.x * (blockDim.x >> 5) + (threadIdx.x >> 5);
    if (t >= N_TOK) return;
    int lane = threadIdx.x & 31;
    float s0 = 0.f, s1 = 0.f, s2 = 0.f;
    for (int j = lane; j < RH_DIM; j += 32) {
        float h = __half2float(g_hid[(size_t)t * RH_DIM + j]);
        s0 += h * rw2[j * 3 + 0];
        s1 += h * rw2[j * 3 + 1];
        s2 += h * rw2[j * 3 + 2];
    }
#pragma unroll
    for (int o = 16; o; o >>= 1) {
        s0 += __shfl_xor_sync(0xFFFFFFFFu, s0, o);
        s1 += __shfl_xor_sync(0xFFFFFFFFu, s1, o);
        s2 += __shfl_xor_sync(0xFFFFFFFFu, s2, o);
    }
    if (lane == 0) {
        s0 += rb2[0]; s1 += rb2[1]; s2 += rb2[2];
        int be = 0;
        float bv = s0, sv = -1e30f;
        if (s1 > bv) { sv = bv; bv = s1; be = 1; } else sv = s1;
        if (s2 > bv) { sv = bv; bv = s2; be = 2; } else if (s2 > sv) sv = s2;
        g_expert[t] = be;
        atomicAdd(&g_cnt[be], 1);
        if (bv - sv < ROUTER_TAU) {
            int i = atomicAdd(&g_nflag, 1);
            g_flaglist[i] = t;
        }
    }
}

// ---------------- fp32 exact router recompute for flagged tokens ----------------
__global__ void __launch_bounds__(RH_DIM) k_fixup(
    const float* __restrict__ x, const float* __restrict__ rw1, const float* __restrict__ rb1,
    const float* __restrict__ rw2, const float* __restrict__ rb2)
{
    __shared__ float sx[C_DIM];
    __shared__ float sh[RH_DIM];
    __shared__ float sl[3];
    int nflag = g_nflag;
    for (int it = blockIdx.x; it < nflag; it += gridDim.x) {
        int t = g_flaglist[it];
        __syncthreads();
        for (int c = threadIdx.x; c < C_DIM; c += RH_DIM) sx[c] = x[(size_t)t * C_DIM + c];
        __syncthreads();
        int j = threadIdx.x;
        float h = rb1[j];
        for (int c = 0; c < C_DIM; c++) h = fmaf(sx[c], rw1[c * RH_DIM + j], h);
        sh[j] = fmaxf(h, 0.f);
        __syncthreads();
        if (threadIdx.x < 3) {
            int ee = threadIdx.x;
            float s = rb2[ee];
            for (int jj = 0; jj < RH_DIM; jj++) s = fmaf(sh[jj], rw2[jj * 3 + ee], s);
            sl[ee] = s;
        }
        __syncthreads();
        if (threadIdx.x == 0) {
            int be = 0;
            float bv = sl[0];
            if (sl[1] > bv) { bv = sl[1]; be = 1; }
            if (sl[2] > bv) { bv = sl[2]; be = 2; }
            int old = g_expert[t];
            if (be != old) {
                g_expert[t] = be;
                atomicSub(&g_cnt[old], 1);
                atomicAdd(&g_cnt[be], 1);
            }
        }
    }
}

// ---------------- routing bookkeeping ----------------
__global__ void k_offsets() {
    if (threadIdx.x == 0) {
        g_off[0] = 0;
        for (int e = 0; e < E_NUM; e++) g_off[e + 1] = g_off[e] + g_cnt[e];
    }
}
__global__ void k_rank() {
    int t = blockIdx.x * blockDim.x + threadIdx.x;
    if (t < N_TOK) {
        int e = g_expert[t];
        int r = atomicAdd(&g_pos[e], 1);
        g_tok_of_rank[g_off[e] + r] = t;
    }
}

// ---------------- launch ----------------
extern "C" void kernel_launch(void* const* d_in, const int* in_sizes, int n_in,
                              void* d_out, int out_size) {
    const float* x = (const float*)d_in[0];
    const float* rw1 = (const float*)d_in[1];
    const float* rb1 = (const float*)d_in[2];
    const float* rw2 = (const float*)d_in[3];
    const float* rb2 = (const float*)d_in[4];
    const float* ew_in = (const float*)d_in[5];
    const float* eb_in = (const float*)d_in[6];
    const float* ew_out = (const float*)d_in[7];
    const float* eb_out = (const float*)d_in[8];
    float* out = (float*)d_out;

    k_init<<<1, 32>>>();

    int n4x = N_TOK * C_DIM / 4;
    k_cast<0><<<(n4x / 2 + 255) / 256, 256>>>((const float4*)x, n4x);
    int n4w1 = C_DIM * RH_DIM / 4;
    k_cast<1><<<(n4w1 / 2 + 255) / 256, 256>>>((const float4*)rw1, n4w1);
    int n4wi = E_NUM * C_DIM * H_DIM / 4;
    k_cast<2><<<(n4wi / 2 + 255) / 256, 256>>>((const float4*)ew_in, n4wi);
    k_cast<3><<<(n4wi / 2 + 255) / 256, 256>>>((const float4*)ew_out, n4wi);

    // router: g_hid = relu(x @ rw1 + rb1)
    dim3 g1(N_TOK / BM, (RH_DIM + BN - 1) / BN, 1);
    k_gemm<0, RH_DIM, C_DIM><<<g1, 256>>>(rb1, nullptr, nullptr);

    k_logits<<<N_TOK / 8, 256>>>(rw2, rb2);
    k_fixup<<<256, RH_DIM>>>(x, rw1, rb1, rw2, rb2);
    k_offsets<<<1, 32>>>();
    k_rank<<<N_TOK / 256, 256>>>();

    // expert GEMM1 (gathers A rows via tok_of_rank): g_h = relu(x16[tok] @ ew_in[e] + eb_in[e])
    dim3 g2(N_TOK / BM, (H_DIM + BN - 1) / BN, E_NUM);
    k_gemm<1, H_DIM, C_DIM><<<g2, 256>>>(eb_in, nullptr, nullptr);

    // expert GEMM2 + residual scatter
    dim3 g3(N_TOK / BM, (C_DIM + BN - 1) / BN, E_NUM);
    k_gemm<2, C_DIM, H_DIM><<<g3, 256>>>(eb_out, x, out);

    (void)in_sizes; (void)n_in; (void)out_size;
}